// round 1
// baseline (speedup 1.0000x reference)
#include <cuda_runtime.h>
#include <math.h>

// BoundaryLoss: exact squared-EDT via separable parabola min-convolution,
// signed distance, softmax-weighted mean.
// Shapes: B=2, C=3, D=H=W=96.

#define DD 96
#define N2 (96*96)        // 9216
#define N3 (96*96*96)     // 884736
#define BIGF 1e8f

// 8 scalar fields: v = (b*2 + (cls-1))*2 + s ; s=0: f=BIG where t==cls (edt(pos))
//                                              s=1: f=BIG where t!=cls (edt(~pos))
__device__ float g_vol[8 * N3];          // ~28.3 MB scratch
__device__ float g_part[1728];           // block partial sums
__device__ int   g_cnt[4];               // mask voxel counts per (b, cls)
__device__ int   g_is32;                 // targets dtype flag (1 = int32, 0 = int64)

// ---------------------------------------------------------------- init helpers
__global__ void k_zero() {
    if (threadIdx.x < 4) g_cnt[threadIdx.x] = 0;
    if (threadIdx.x == 4) g_is32 = 0;
}

// Detect whether targets buffer is int32 or int64: for int64 values in [0,2],
// every odd int32 word (high half) is 0. Check first 4096 odd words
// (false-negative prob (1/3)^4096 ~ 0). Reading N int32s is safe either way.
__global__ void k_detect(const int* __restrict__ t32) {
    int any = 0;
    #pragma unroll
    for (int u = 0; u < 16; u++) {
        int k = threadIdx.x + 256 * u;
        if (t32[2 * k + 1] != 0) any = 1;
    }
    int r = __syncthreads_or(any);
    if (threadIdx.x == 0) g_is32 = r ? 1 : 0;
}

// Initialize the 8 fields + count mask voxels. Grid: 6912 blocks x 256
// (blocks [0,3456) -> b=0, [3456,6912) -> b=1).
__global__ void k_init(const void* __restrict__ tptr) {
    int b = blockIdx.x / 3456;
    int n = (blockIdx.x % 3456) * 256 + threadIdx.x;
    int t;
    if (g_is32) t = ((const int*)tptr)[b * N3 + n];
    else        t = (int)((const long long*)tptr)[b * N3 + n];

    g_vol[(size_t)(b * 4 + 0) * N3 + n] = (t == 1) ? BIGF : 0.f;
    g_vol[(size_t)(b * 4 + 1) * N3 + n] = (t == 1) ? 0.f : BIGF;
    g_vol[(size_t)(b * 4 + 2) * N3 + n] = (t == 2) ? BIGF : 0.f;
    g_vol[(size_t)(b * 4 + 3) * N3 + n] = (t == 2) ? 0.f : BIGF;

    int c1 = (t == 1), c2 = (t == 2);
    #pragma unroll
    for (int off = 16; off; off >>= 1) {
        c1 += __shfl_down_sync(0xffffffffu, c1, off);
        c2 += __shfl_down_sync(0xffffffffu, c2, off);
    }
    __shared__ int s1[8], s2[8];
    if ((threadIdx.x & 31) == 0) { s1[threadIdx.x >> 5] = c1; s2[threadIdx.x >> 5] = c2; }
    __syncthreads();
    if (threadIdx.x == 0) {
        int t1 = 0, t2 = 0;
        #pragma unroll
        for (int i = 0; i < 8; i++) { t1 += s1[i]; t2 += s2[i]; }
        atomicAdd(&g_cnt[b * 2 + 0], t1);
        atomicAdd(&g_cnt[b * 2 + 1], t2);
    }
}

// ---------------------------------------------------------------- minconv W
// Lines along W are contiguous. Each block owns 768 contiguous floats
// (8 lines). Warp w handles line w; lane x computes outputs x, x+32, x+64.
// In-place (read via shared). Grid: 8*N3/768 = 9216 blocks x 256.
__global__ void k_pass_w() {
    __shared__ float sh[768];
    int tid = threadIdx.x;
    int base = blockIdx.x * 768;
    sh[tid]       = g_vol[base + tid];
    sh[tid + 256] = g_vol[base + tid + 256];
    sh[tid + 512] = g_vol[base + tid + 512];
    __syncthreads();
    int l = tid >> 5, x = tid & 31;
    const float* f = sh + l * 96;
    float v0 = 3.4e38f, v1 = 3.4e38f, v2 = 3.4e38f;
    float d0 = (float)x, d1 = (float)(x + 32), d2 = (float)(x + 64);
    #pragma unroll 8
    for (int j = 0; j < 96; j++) {
        float s = f[j];
        v0 = fminf(v0, fmaf(d0, d0, s)); d0 -= 1.f;
        v1 = fminf(v1, fmaf(d1, d1, s)); d1 -= 1.f;
        v2 = fminf(v2, fmaf(d2, d2, s)); d2 -= 1.f;
    }
    g_vol[base + l * 96 + x]      = v0;
    g_vol[base + l * 96 + x + 32] = v1;
    g_vol[base + l * 96 + x + 64] = v2;
}

// ---------------------------------------------------------------- minconv H/D
// Strided-axis pass via 96x32 shared tile for fully coalesced gmem access.
// STRIDE = element stride along the minconv axis (96 for H, N2 for D)
// SLICE  = stride of the per-block fixed slice index (N2 for H, 96 for D)
// Grid: 8 vols * 96 slices * 3 w-chunks = 2304 blocks x 256 (32x8).
template<int STRIDE, int SLICE>
__global__ void k_pass_s() {
    __shared__ float sh[96 * 32];   // 12 KB, bank-conflict-free (bank = tx)
    int bid = blockIdx.x;
    int vb = bid / 288, rem = bid % 288;
    int s = rem / 3, wc = rem % 3;
    int base = vb * N3 + s * SLICE + wc * 32;
    int tx = threadIdx.x & 31, ty = threadIdx.x >> 5;

    #pragma unroll
    for (int r = ty; r < 96; r += 8)
        sh[r * 32 + tx] = g_vol[base + r * STRIDE + tx];
    __syncthreads();

    float v[12], dd[12];
    #pragma unroll
    for (int k = 0; k < 12; k++) { v[k] = 3.4e38f; dd[k] = (float)(ty + 8 * k); }
    for (int j = 0; j < 96; j++) {
        float sv = sh[j * 32 + tx];
        #pragma unroll
        for (int k = 0; k < 12; k++) {
            v[k] = fminf(v[k], fmaf(dd[k], dd[k], sv));
            dd[k] -= 1.f;
        }
    }
    #pragma unroll
    for (int k = 0; k < 12; k++)
        g_vol[base + (ty + 8 * k) * STRIDE + tx] = v[k];
}

// ---------------------------------------------------------------- reduction
// Fused: softmax over 3 channels + sqrt of squared EDTs + signed dist + gate,
// accumulate probs*sd. Grid: 1728 blocks x 256, 4 voxels/thread (strided).
__global__ void k_reduce(const float* __restrict__ logits) {
    int g = blockIdx.x * 256 + threadIdx.x;
    float gca = g_cnt[0] > 0 ? 1.f : 0.f;
    float gcb = g_cnt[1] > 0 ? 1.f : 0.f;
    float gcc = g_cnt[2] > 0 ? 1.f : 0.f;
    float gcd = g_cnt[3] > 0 ? 1.f : 0.f;
    float acc = 0.f;
    #pragma unroll
    for (int u = 0; u < 4; u++) {
        int idx = g + u * 442368;           // < 2*N3
        int b = idx / N3;
        int n = idx - b * N3;
        const float* L = logits + (size_t)b * 3 * N3 + n;
        float l0 = L[0], l1 = L[N3], l2 = L[2 * N3];
        float m = fmaxf(l0, fmaxf(l1, l2));
        float e0 = __expf(l0 - m), e1 = __expf(l1 - m), e2 = __expf(l2 - m);
        float inv = 1.f / (e0 + e1 + e2);
        const float* V = g_vol + (size_t)b * 4 * N3 + n;
        float sd1 = sqrtf(V[(size_t)N3]) - sqrtf(V[0]);
        float sd2 = sqrtf(V[(size_t)3 * N3]) - sqrtf(V[(size_t)2 * N3]);
        float g1 = b ? gcc : gca;
        float g2 = b ? gcd : gcb;
        acc += inv * (e1 * sd1 * g1 + e2 * sd2 * g2);
    }
    // deterministic block reduction
    #pragma unroll
    for (int off = 16; off; off >>= 1)
        acc += __shfl_down_sync(0xffffffffu, acc, off);
    __shared__ float sw[8];
    if ((threadIdx.x & 31) == 0) sw[threadIdx.x >> 5] = acc;
    __syncthreads();
    if (threadIdx.x == 0) {
        float t = 0.f;
        #pragma unroll
        for (int i = 0; i < 8; i++) t += sw[i];
        g_part[blockIdx.x] = t;
    }
}

__global__ void k_final(float* __restrict__ out) {
    __shared__ double sm[256];
    double s = 0.0;
    for (int i = threadIdx.x; i < 1728; i += 256) s += (double)g_part[i];
    sm[threadIdx.x] = s;
    __syncthreads();
    #pragma unroll
    for (int off = 128; off > 0; off >>= 1) {
        if (threadIdx.x < off) sm[threadIdx.x] += sm[threadIdx.x + off];
        __syncthreads();
    }
    if (threadIdx.x == 0)
        out[0] = (float)(sm[0] / (2.0 * (double)N3));   // / (B * D*H*W)
}

// ---------------------------------------------------------------- launch
extern "C" void kernel_launch(void* const* d_in, const int* in_sizes, int n_in,
                              void* d_out, int out_size) {
    const float* logits = (const float*)d_in[0];
    const void*  targets = d_in[1];
    float* out = (float*)d_out;
    (void)in_sizes; (void)n_in; (void)out_size;

    k_zero<<<1, 32>>>();
    k_detect<<<1, 256>>>((const int*)targets);
    k_init<<<6912, 256>>>(targets);
    k_pass_w<<<9216, 256>>>();
    k_pass_s<96, N2><<<2304, 256>>>();   // H axis
    k_pass_s<N2, 96><<<2304, 256>>>();   // D axis
    k_reduce<<<1728, 256>>>(logits);
    k_final<<<1, 256>>>(out);
}

// round 2
// speedup vs baseline: 2.8718x; 2.8718x over previous
#include <cuda_runtime.h>
#include <math.h>

// BoundaryLoss: exact squared-EDT via separable min-convolution.
// Pass W: bit-trick nearest-zero (input binary). Passes H/D: exact windowed
// parabola min-conv (window provably sufficient: g[i] <= f[i]).
// Shapes: B=2, C=3, D=H=W=96.

#define N2 9216           // 96*96
#define N3 884736         // 96^3
#define BIGF 1e8f

// 8 fields: v = b*4 + (cls-1)*2 + s ; s=0: edt(pos), s=1: edt(~pos)
__device__ float g_vol[8 * N3];          // ~28.3 MB scratch
__device__ float g_part[1728];
__device__ int   g_cnt[4];
__device__ int   g_is32;

// ------------------------------------------------------------- dtype detect
// int64 targets in [0,2] -> all odd int32 words zero.
__global__ void k_detect(const int* __restrict__ t32) {
    if (threadIdx.x < 4) g_cnt[threadIdx.x] = 0;
    int any = 0;
    #pragma unroll
    for (int u = 0; u < 16; u++) {
        int k = threadIdx.x + 256 * u;
        if (t32[2 * k + 1] != 0) any = 1;
    }
    int r = __syncthreads_or(any);
    if (threadIdx.x == 0) g_is32 = r ? 1 : 0;
}

// ------------------------------------------------- fused init + W-axis pass
// For binary input f in {0,BIG}: g[i] = d^2 with d = distance to nearest
// zero of f along the 96-long line; g = BIG if no zero exists.
// Nearest zero via 96-bit mask (3 ballot words) + clz/ffs.
// One warp per (b, d, h) line; computes all 4 fields (cls x polarity).
__device__ __forceinline__ int near_zero_dist(unsigned z0, unsigned z1, unsigned z2,
                                              int w, int r) {
    unsigned lowm = (2u << r) - 1u;          // bits [0..r]
    unsigned him  = 0xffffffffu << r;        // bits [r..31]
    int dl = 1000, dr = 1000;
    if (w == 0) {
        unsigned u = z0 & lowm;
        if (u) dl = r - (31 - __clz(u));
        unsigned v = z0 & him;
        if (v)       dr = (__ffs(v) - 1) - r;
        else if (z1) dr = 32 - r + (__ffs(z1) - 1);
        else if (z2) dr = 64 - r + (__ffs(z2) - 1);
    } else if (w == 1) {
        unsigned u = z1 & lowm;
        if (u)       dl = r - (31 - __clz(u));
        else if (z0) dl = r + 1 + __clz(z0);
        unsigned v = z1 & him;
        if (v)       dr = (__ffs(v) - 1) - r;
        else if (z2) dr = 32 - r + (__ffs(z2) - 1);
    } else {
        unsigned u = z2 & lowm;
        if (u)       dl = r - (31 - __clz(u));
        else if (z1) dl = r + 1 + __clz(z1);
        else if (z0) dl = r + 33 + __clz(z0);
        unsigned v = z2 & him;
        if (v) dr = (__ffs(v) - 1) - r;
    }
    return min(dl, dr);
}

__global__ void k_binw(const void* __restrict__ tptr) {
    int wid = threadIdx.x >> 5, l = threadIdx.x & 31;
    int L = blockIdx.x * 8 + wid;        // 0..18431 : (b, line)
    int b = L / 9216;
    int n = L - b * 9216;
    int base = b * N3 + n * 96;

    int t0, t1, t2;
    if (g_is32) {
        const int* T = (const int*)tptr;
        t0 = T[base + l]; t1 = T[base + l + 32]; t2 = T[base + l + 64];
    } else {
        const long long* T = (const long long*)tptr;
        t0 = (int)T[base + l]; t1 = (int)T[base + l + 32]; t2 = (int)T[base + l + 64];
    }
    unsigned m1_0 = __ballot_sync(0xffffffffu, t0 == 1);
    unsigned m1_1 = __ballot_sync(0xffffffffu, t1 == 1);
    unsigned m1_2 = __ballot_sync(0xffffffffu, t2 == 1);
    unsigned m2_0 = __ballot_sync(0xffffffffu, t0 == 2);
    unsigned m2_1 = __ballot_sync(0xffffffffu, t1 == 2);
    unsigned m2_2 = __ballot_sync(0xffffffffu, t2 == 2);

    // mask voxel counts (block-aggregated; block is uniform in b: 9216%8==0)
    __shared__ int sc[2];
    if (threadIdx.x < 2) sc[threadIdx.x] = 0;
    __syncthreads();
    if (l == 0) {
        atomicAdd(&sc[0], __popc(m1_0) + __popc(m1_1) + __popc(m1_2));
        atomicAdd(&sc[1], __popc(m2_0) + __popc(m2_1) + __popc(m2_2));
    }
    __syncthreads();
    if (threadIdx.x == 0) {
        atomicAdd(&g_cnt[b * 2 + 0], sc[0]);
        atomicAdd(&g_cnt[b * 2 + 1], sc[1]);
    }

    // 4 fields: zeros of field f are where the binary is False.
    // s=0 (edt(pos)): BIG where t==cls -> zeros at ~m ; s=1: zeros at m.
    #pragma unroll
    for (int ff = 0; ff < 4; ff++) {
        unsigned z0, z1, z2;
        if      (ff == 0) { z0 = ~m1_0; z1 = ~m1_1; z2 = ~m1_2; }
        else if (ff == 1) { z0 =  m1_0; z1 =  m1_1; z2 =  m1_2; }
        else if (ff == 2) { z0 = ~m2_0; z1 = ~m2_1; z2 = ~m2_2; }
        else              { z0 =  m2_0; z1 =  m2_1; z2 =  m2_2; }
        float* out = g_vol + (size_t)(b * 4 + ff) * N3 + n * 96;
        int d0 = near_zero_dist(z0, z1, z2, 0, l);
        int d1 = near_zero_dist(z0, z1, z2, 1, l);
        int d2 = near_zero_dist(z0, z1, z2, 2, l);
        out[l]      = (d0 > 95) ? BIGF : (float)(d0 * d0);
        out[l + 32] = (d1 > 95) ? BIGF : (float)(d1 * d1);
        out[l + 64] = (d2 > 95) ? BIGF : (float)(d2 * d2);
    }
}

// ------------------------------------------------- windowed min-conv (H/D)
// g[i] = min_j f[j] + (i-j)^2 = i^2 + min_j (f[j]+j^2 - 2ij).
// Exact window: since g[i] <= f[i], j with (i-j)^2 > f[i] never wins ->
// R = floor(sqrt(max_tile f)) + 1 suffices; BIG in tile -> full window.
// Block: 32 lines (tx) x 96 outputs (ty*12 + k, contiguous per thread).
template<int STRIDE, int SLICE>
__global__ void k_pass_s() {
    __shared__ float sh[96 * 32];     // fj2 tile, bank-conflict-free
    __shared__ float smax_s[8];
    __shared__ int sR;
    int bid = blockIdx.x;
    int vb = bid / 288, rem = bid % 288;
    int s = rem / 3, wc = rem % 3;
    size_t base = (size_t)vb * N3 + s * SLICE + wc * 32;
    int tx = threadIdx.x & 31, ty = threadIdx.x >> 5;

    float mx = 0.f;
    #pragma unroll
    for (int r = ty; r < 96; r += 8) {
        float f = g_vol[base + (size_t)r * STRIDE + tx];
        mx = fmaxf(mx, f);
        sh[r * 32 + tx] = f + (float)(r * r);
    }
    #pragma unroll
    for (int off = 16; off; off >>= 1)
        mx = fmaxf(mx, __shfl_xor_sync(0xffffffffu, mx, off));
    if (tx == 0) smax_s[ty] = mx;
    __syncthreads();
    if (threadIdx.x == 0) {
        float m = smax_s[0];
        #pragma unroll
        for (int i = 1; i < 8; i++) m = fmaxf(m, smax_s[i]);
        int R = (m >= 1e7f) ? 95 : ((int)floorf(sqrtf(m)) + 1);
        sR = min(R, 95);
    }
    __syncthreads();
    int R = sR;

    int i0 = ty * 12;
    int j0 = max(0, i0 - R);
    int j1 = min(95, i0 + 11 + R);

    float v[12], fi[12];
    #pragma unroll
    for (int k = 0; k < 12; k++) { v[k] = 3.0e38f; fi[k] = (float)(i0 + k); }

    const float* shp = sh + tx;
    float m2j = -2.0f * (float)j0;
    float fj2 = shp[j0 * 32];
    for (int j = j0; j <= j1; j++) {
        float nxt = shp[min(j + 1, 95) * 32];   // prefetch
        #pragma unroll
        for (int k = 0; k < 12; k++)
            v[k] = fminf(v[k], fmaf(m2j, fi[k], fj2));
        m2j -= 2.f;
        fj2 = nxt;
    }

    #pragma unroll
    for (int k = 0; k < 12; k++)
        g_vol[base + (size_t)(i0 + k) * STRIDE + tx] = v[k] + fi[k] * fi[k];
}

// ---------------------------------------------------------------- reduction
__global__ void k_reduce(const float* __restrict__ logits) {
    int g = blockIdx.x * 256 + threadIdx.x;
    float gca = g_cnt[0] > 0 ? 1.f : 0.f;
    float gcb = g_cnt[1] > 0 ? 1.f : 0.f;
    float gcc = g_cnt[2] > 0 ? 1.f : 0.f;
    float gcd = g_cnt[3] > 0 ? 1.f : 0.f;
    float acc = 0.f;
    #pragma unroll
    for (int u = 0; u < 4; u++) {
        int idx = g + u * 442368;
        int b = idx / N3;
        int n = idx - b * N3;
        const float* L = logits + (size_t)b * 3 * N3 + n;
        float l0 = L[0], l1 = L[N3], l2 = L[2 * N3];
        float m = fmaxf(l0, fmaxf(l1, l2));
        float e0 = __expf(l0 - m), e1 = __expf(l1 - m), e2 = __expf(l2 - m);
        float inv = 1.f / (e0 + e1 + e2);
        const float* V = g_vol + (size_t)b * 4 * N3 + n;
        float sd1 = sqrtf(V[(size_t)N3]) - sqrtf(V[0]);
        float sd2 = sqrtf(V[(size_t)3 * N3]) - sqrtf(V[(size_t)2 * N3]);
        float g1 = b ? gcc : gca;
        float g2 = b ? gcd : gcb;
        acc += inv * (e1 * sd1 * g1 + e2 * sd2 * g2);
    }
    #pragma unroll
    for (int off = 16; off; off >>= 1)
        acc += __shfl_down_sync(0xffffffffu, acc, off);
    __shared__ float sw[8];
    if ((threadIdx.x & 31) == 0) sw[threadIdx.x >> 5] = acc;
    __syncthreads();
    if (threadIdx.x == 0) {
        float t = 0.f;
        #pragma unroll
        for (int i = 0; i < 8; i++) t += sw[i];
        g_part[blockIdx.x] = t;
    }
}

__global__ void k_final(float* __restrict__ out) {
    __shared__ double sm[256];
    double s = 0.0;
    for (int i = threadIdx.x; i < 1728; i += 256) s += (double)g_part[i];
    sm[threadIdx.x] = s;
    __syncthreads();
    #pragma unroll
    for (int off = 128; off > 0; off >>= 1) {
        if (threadIdx.x < off) sm[threadIdx.x] += sm[threadIdx.x + off];
        __syncthreads();
    }
    if (threadIdx.x == 0)
        out[0] = (float)(sm[0] / (2.0 * (double)N3));
}

// ---------------------------------------------------------------- launch
extern "C" void kernel_launch(void* const* d_in, const int* in_sizes, int n_in,
                              void* d_out, int out_size) {
    const float* logits = (const float*)d_in[0];
    const void*  targets = d_in[1];
    float* out = (float*)d_out;
    (void)in_sizes; (void)n_in; (void)out_size;

    k_detect<<<1, 256>>>((const int*)targets);
    k_binw<<<2304, 256>>>(targets);
    k_pass_s<96, N2><<<2304, 256>>>();   // H axis
    k_pass_s<N2, 96><<<2304, 256>>>();   // D axis
    k_reduce<<<1728, 256>>>(logits);
    k_final<<<1, 256>>>(out);
}

// round 3
// speedup vs baseline: 3.1030x; 1.0805x over previous
#include <cuda_runtime.h>
#include <math.h>

// BoundaryLoss: exact squared-EDT via separable min-convolution.
// W pass: bit-trick nearest-zero fused with init (u16 output).
// H pass: exact windowed parabola min-conv, u16 in/out.
// D pass: windowed min-conv fused with softmax + signed-dist + reduction.
// Shapes: B=2, C=3, D=H=W=96.

#define N2 9216           // 96*96
#define N3 884736         // 96^3
#define BIGF 1e8f
#define SENT 65535u

// 8 fields: v = b*4 + (cls-1)*2 + s ; s=0: edt(pos), s=1: edt(~pos)
__device__ unsigned short g_u16[8 * N3];   // 14.2 MB scratch (exact ints + sentinel)
__device__ float g_part[576];
__device__ int   g_cnt[4];
__device__ int   g_is32;

// ------------------------------------------------------------- dtype detect
__global__ void k_detect(const int* __restrict__ t32) {
    if (threadIdx.x < 4) g_cnt[threadIdx.x] = 0;
    int any = 0;
    #pragma unroll
    for (int u = 0; u < 16; u++) {
        int k = threadIdx.x + 256 * u;
        if (t32[2 * k + 1] != 0) any = 1;
    }
    int r = __syncthreads_or(any);
    if (threadIdx.x == 0) g_is32 = r ? 1 : 0;
}

// ------------------------------------------------- fused init + W-axis pass
__device__ __forceinline__ int near_zero_dist(unsigned z0, unsigned z1, unsigned z2,
                                              int w, int r) {
    unsigned lowm = (2u << r) - 1u;
    unsigned him  = 0xffffffffu << r;
    int dl = 1000, dr = 1000;
    if (w == 0) {
        unsigned u = z0 & lowm;
        if (u) dl = r - (31 - __clz(u));
        unsigned v = z0 & him;
        if (v)       dr = (__ffs(v) - 1) - r;
        else if (z1) dr = 32 - r + (__ffs(z1) - 1);
        else if (z2) dr = 64 - r + (__ffs(z2) - 1);
    } else if (w == 1) {
        unsigned u = z1 & lowm;
        if (u)       dl = r - (31 - __clz(u));
        else if (z0) dl = r + 1 + __clz(z0);
        unsigned v = z1 & him;
        if (v)       dr = (__ffs(v) - 1) - r;
        else if (z2) dr = 32 - r + (__ffs(z2) - 1);
    } else {
        unsigned u = z2 & lowm;
        if (u)       dl = r - (31 - __clz(u));
        else if (z1) dl = r + 1 + __clz(z1);
        else if (z0) dl = r + 33 + __clz(z0);
        unsigned v = z2 & him;
        if (v) dr = (__ffs(v) - 1) - r;
    }
    return min(dl, dr);
}

__global__ void __launch_bounds__(256) k_binw(const void* __restrict__ tptr) {
    int wid = threadIdx.x >> 5, l = threadIdx.x & 31;
    int L = blockIdx.x * 8 + wid;
    int b = L / 9216;
    int n = L - b * 9216;
    int base = b * N3 + n * 96;

    int t0, t1, t2;
    if (g_is32) {
        const int* T = (const int*)tptr;
        t0 = T[base + l]; t1 = T[base + l + 32]; t2 = T[base + l + 64];
    } else {
        const long long* T = (const long long*)tptr;
        t0 = (int)T[base + l]; t1 = (int)T[base + l + 32]; t2 = (int)T[base + l + 64];
    }
    unsigned m1_0 = __ballot_sync(0xffffffffu, t0 == 1);
    unsigned m1_1 = __ballot_sync(0xffffffffu, t1 == 1);
    unsigned m1_2 = __ballot_sync(0xffffffffu, t2 == 1);
    unsigned m2_0 = __ballot_sync(0xffffffffu, t0 == 2);
    unsigned m2_1 = __ballot_sync(0xffffffffu, t1 == 2);
    unsigned m2_2 = __ballot_sync(0xffffffffu, t2 == 2);

    __shared__ int sc[2];
    if (threadIdx.x < 2) sc[threadIdx.x] = 0;
    __syncthreads();
    if (l == 0) {
        atomicAdd(&sc[0], __popc(m1_0) + __popc(m1_1) + __popc(m1_2));
        atomicAdd(&sc[1], __popc(m2_0) + __popc(m2_1) + __popc(m2_2));
    }
    __syncthreads();
    if (threadIdx.x == 0) {
        atomicAdd(&g_cnt[b * 2 + 0], sc[0]);
        atomicAdd(&g_cnt[b * 2 + 1], sc[1]);
    }

    #pragma unroll
    for (int ff = 0; ff < 4; ff++) {
        unsigned z0, z1, z2;
        if      (ff == 0) { z0 = ~m1_0; z1 = ~m1_1; z2 = ~m1_2; }
        else if (ff == 1) { z0 =  m1_0; z1 =  m1_1; z2 =  m1_2; }
        else if (ff == 2) { z0 = ~m2_0; z1 = ~m2_1; z2 = ~m2_2; }
        else              { z0 =  m2_0; z1 =  m2_1; z2 =  m2_2; }
        unsigned short* out = g_u16 + (size_t)(b * 4 + ff) * N3 + n * 96;
        int d0 = near_zero_dist(z0, z1, z2, 0, l);
        int d1 = near_zero_dist(z0, z1, z2, 1, l);
        int d2 = near_zero_dist(z0, z1, z2, 2, l);
        out[l]      = (d0 > 95) ? SENT : (unsigned short)(d0 * d0);
        out[l + 32] = (d1 > 95) ? SENT : (unsigned short)(d1 * d1);
        out[l + 64] = (d2 > 95) ? SENT : (unsigned short)(d2 * d2);
    }
}

// ------------------------------------------------- windowed min-conv core
// v[k] = min over j in [j0,j1] of (f[j]+j^2) - 2*j*i ; caller adds i^2.
__device__ __forceinline__ void minconv12(const float* __restrict__ shp,
                                          int j0, int j1,
                                          const float fi[12], float v[12]) {
    float m2a = -2.0f * (float)j0;
    int j = j0;
    for (; j + 1 <= j1; j += 2) {
        float a = shp[j * 32];
        float b = shp[j * 32 + 32];
        float m2b = m2a - 2.0f;
        #pragma unroll
        for (int k = 0; k < 12; k++)
            v[k] = fminf(v[k], fmaf(m2a, fi[k], a));
        #pragma unroll
        for (int k = 0; k < 12; k++)
            v[k] = fminf(v[k], fmaf(m2b, fi[k], b));
        m2a -= 4.0f;
    }
    if (j == j1) {
        float a = shp[j * 32];
        #pragma unroll
        for (int k = 0; k < 12; k++)
            v[k] = fminf(v[k], fmaf(m2a, fi[k], a));
    }
}

__device__ __forceinline__ int win_from_max(float m) {
    int R = (m >= 1e7f) ? 95 : ((int)floorf(sqrtf(m)) + 1);
    return min(R, 95);
}

// ---------------------------------------------------------------- H pass
// Grid: 8 vols * 96 d-slices * 3 w-chunks = 2304 blocks x 256.
__global__ void __launch_bounds__(256) k_pass_h() {
    __shared__ float sh[96 * 32];
    __shared__ int smax;
    int bid = blockIdx.x;
    int vb = bid / 288, rem = bid % 288;
    int s = rem / 3, wc = rem % 3;
    size_t base = (size_t)vb * N3 + (size_t)s * N2 + wc * 32;
    int tx = threadIdx.x & 31, ty = threadIdx.x >> 5;

    if (threadIdx.x == 0) smax = 0;
    __syncthreads();
    float mx = 0.f;
    #pragma unroll
    for (int r = ty; r < 96; r += 8) {
        unsigned u = g_u16[base + r * 96 + tx];
        float f = (u == SENT) ? BIGF : (float)u;
        mx = fmaxf(mx, f);
        sh[r * 32 + tx] = f + (float)(r * r);
    }
    #pragma unroll
    for (int off = 16; off; off >>= 1)
        mx = fmaxf(mx, __shfl_xor_sync(0xffffffffu, mx, off));
    if (tx == 0) atomicMax(&smax, __float_as_int(mx));
    __syncthreads();
    int R = win_from_max(__int_as_float(smax));

    int i0 = ty * 12;
    int j0 = max(0, i0 - R);
    int j1 = min(95, i0 + 11 + R);

    float v[12], fi[12];
    #pragma unroll
    for (int k = 0; k < 12; k++) { v[k] = 3.0e38f; fi[k] = (float)(i0 + k); }
    minconv12(sh + tx, j0, j1, fi, v);

    unsigned short* outp = g_u16 + base + (size_t)i0 * 96 + tx;
    #pragma unroll
    for (int k = 0; k < 12; k++) {
        float vi = v[k] + fi[k] * fi[k];
        outp[k * 96] = (vi >= 1e7f) ? SENT : (unsigned short)__float2int_rn(vi);
    }
}

// ------------------------------------------- fused D pass + softmax reduce
// Grid: 2(b) * 96(h-slice) * 3(w-chunk) = 576 blocks x 256.
// Each block: 4 fields (cls1 pos/neg, cls2 pos/neg) for its 96(d) x 32(w) tile.
__global__ void __launch_bounds__(256) k_fuse_d(const float* __restrict__ logits) {
    __shared__ float sh0[96 * 32];
    __shared__ float sh1[96 * 32];
    __shared__ int smaxi[4];
    __shared__ float swred[8];
    int bid = blockIdx.x;
    int b = bid / 288, rem = bid % 288;
    int s = rem / 3, wc = rem % 3;
    int tx = threadIdx.x & 31, ty = threadIdx.x >> 5;
    unsigned nbase = (unsigned)s * 96 + wc * 32 + tx;   // voxel idx: + d*N2

    if (threadIdx.x < 4) smaxi[threadIdx.x] = 0;
    __syncthreads();

    int i0 = ty * 12;
    float fi[12];
    #pragma unroll
    for (int k = 0; k < 12; k++) fi[k] = (float)(i0 + k);

    float sd1[12], sd2[12];

    #pragma unroll
    for (int pair = 0; pair < 2; pair++) {
        // load pos/neg tiles (d is the row axis, stride N2)
        size_t vbase0 = (size_t)(b * 4 + pair * 2) * N3 + nbase - tx + tx; // keep simple
        const unsigned short* p0 = g_u16 + (size_t)(b * 4 + pair * 2 + 0) * N3 + nbase;
        const unsigned short* p1 = g_u16 + (size_t)(b * 4 + pair * 2 + 1) * N3 + nbase;
        (void)vbase0;
        float mx0 = 0.f, mx1 = 0.f;
        #pragma unroll
        for (int r = ty; r < 96; r += 8) {
            unsigned u0 = p0[(size_t)r * N2];
            unsigned u1 = p1[(size_t)r * N2];
            float f0 = (u0 == SENT) ? BIGF : (float)u0;
            float f1 = (u1 == SENT) ? BIGF : (float)u1;
            mx0 = fmaxf(mx0, f0); mx1 = fmaxf(mx1, f1);
            float r2 = (float)(r * r);
            sh0[r * 32 + tx] = f0 + r2;
            sh1[r * 32 + tx] = f1 + r2;
        }
        #pragma unroll
        for (int off = 16; off; off >>= 1) {
            mx0 = fmaxf(mx0, __shfl_xor_sync(0xffffffffu, mx0, off));
            mx1 = fmaxf(mx1, __shfl_xor_sync(0xffffffffu, mx1, off));
        }
        if (tx == 0) {
            atomicMax(&smaxi[pair * 2 + 0], __float_as_int(mx0));
            atomicMax(&smaxi[pair * 2 + 1], __float_as_int(mx1));
        }
        __syncthreads();
        int R0 = win_from_max(__int_as_float(smaxi[pair * 2 + 0]));
        int R1 = win_from_max(__int_as_float(smaxi[pair * 2 + 1]));

        float* sd = pair ? sd2 : sd1;
        float v[12];
        // pos field
        #pragma unroll
        for (int k = 0; k < 12; k++) v[k] = 3.0e38f;
        minconv12(sh0 + tx, max(0, i0 - R0), min(95, i0 + 11 + R0), fi, v);
        #pragma unroll
        for (int k = 0; k < 12; k++) sd[k] = -sqrtf(v[k] + fi[k] * fi[k]);
        // neg field
        #pragma unroll
        for (int k = 0; k < 12; k++) v[k] = 3.0e38f;
        minconv12(sh1 + tx, max(0, i0 - R1), min(95, i0 + 11 + R1), fi, v);
        #pragma unroll
        for (int k = 0; k < 12; k++) sd[k] += sqrtf(v[k] + fi[k] * fi[k]);
        if (pair == 0) __syncthreads();   // before tile overwrite
    }

    // epilogue: softmax + gated weighted accumulate
    float g1 = g_cnt[b * 2 + 0] > 0 ? 1.f : 0.f;
    float g2 = g_cnt[b * 2 + 1] > 0 ? 1.f : 0.f;
    const float* L = logits + (size_t)b * 3 * N3 + nbase + (size_t)i0 * N2;
    float acc = 0.f;
    #pragma unroll
    for (int k = 0; k < 12; k++) {
        float l0 = L[0], l1 = L[(size_t)N3], l2 = L[(size_t)2 * N3];
        L += N2;
        float m = fmaxf(l0, fmaxf(l1, l2));
        float e0 = __expf(l0 - m), e1 = __expf(l1 - m), e2 = __expf(l2 - m);
        float inv = 1.f / (e0 + e1 + e2);
        acc += inv * (e1 * sd1[k] * g1 + e2 * sd2[k] * g2);
    }

    #pragma unroll
    for (int off = 16; off; off >>= 1)
        acc += __shfl_down_sync(0xffffffffu, acc, off);
    if (tx == 0) swred[ty] = acc;
    __syncthreads();
    if (threadIdx.x == 0) {
        float t = 0.f;
        #pragma unroll
        for (int i = 0; i < 8; i++) t += swred[i];
        g_part[bid] = t;
    }
}

// ---------------------------------------------------------------- final
__global__ void k_final(float* __restrict__ out) {
    __shared__ double sm[256];
    double s = 0.0;
    for (int i = threadIdx.x; i < 576; i += 256) s += (double)g_part[i];
    sm[threadIdx.x] = s;
    __syncthreads();
    #pragma unroll
    for (int off = 128; off > 0; off >>= 1) {
        if (threadIdx.x < off) sm[threadIdx.x] += sm[threadIdx.x + off];
        __syncthreads();
    }
    if (threadIdx.x == 0)
        out[0] = (float)(sm[0] / (2.0 * (double)N3));
}

// ---------------------------------------------------------------- launch
extern "C" void kernel_launch(void* const* d_in, const int* in_sizes, int n_in,
                              void* d_out, int out_size) {
    const float* logits = (const float*)d_in[0];
    const void*  targets = d_in[1];
    float* out = (float*)d_out;
    (void)in_sizes; (void)n_in; (void)out_size;

    k_detect<<<1, 256>>>((const int*)targets);
    k_binw<<<2304, 256>>>(targets);
    k_pass_h<<<2304, 256>>>();
    k_fuse_d<<<576, 256>>>(logits);
    k_final<<<1, 256>>>(out);
}

// round 4
// speedup vs baseline: 3.1233x; 1.0065x over previous
#include <cuda_runtime.h>
#include <math.h>

// BoundaryLoss: exact squared-EDT via separable min-convolution.
// W pass: bit-trick nearest-zero fused with init (u16 output).
// H pass: exact windowed parabola min-conv, u16 in/out.
// D pass: windowed min-conv fused with softmax + signed-dist + reduction,
//         split per (b, cls) pair for occupancy.
// Shapes: B=2, C=3, D=H=W=96.

#define N2 9216           // 96*96
#define N3 884736         // 96^3
#define BIGF 1e8f
#define SENT 65535u

// 8 fields: v = b*4 + (cls-1)*2 + s ; s=0: edt(pos), s=1: edt(~pos)
__device__ unsigned short g_u16[8 * N3];   // 14.2 MB scratch (exact ints + sentinel)
__device__ float g_part[1152];
__device__ int   g_cnt[4];
__device__ int   g_is32;

// ------------------------------------------------------------- dtype detect
__global__ void k_detect(const int* __restrict__ t32) {
    if (threadIdx.x < 4) g_cnt[threadIdx.x] = 0;
    int any = 0;
    #pragma unroll
    for (int u = 0; u < 16; u++) {
        int k = threadIdx.x + 256 * u;
        if (t32[2 * k + 1] != 0) any = 1;
    }
    int r = __syncthreads_or(any);
    if (threadIdx.x == 0) g_is32 = r ? 1 : 0;
}

// ------------------------------------------------- fused init + W-axis pass
__device__ __forceinline__ int near_zero_dist(unsigned z0, unsigned z1, unsigned z2,
                                              int w, int r) {
    unsigned lowm = (2u << r) - 1u;
    unsigned him  = 0xffffffffu << r;
    int dl = 1000, dr = 1000;
    if (w == 0) {
        unsigned u = z0 & lowm;
        if (u) dl = r - (31 - __clz(u));
        unsigned v = z0 & him;
        if (v)       dr = (__ffs(v) - 1) - r;
        else if (z1) dr = 32 - r + (__ffs(z1) - 1);
        else if (z2) dr = 64 - r + (__ffs(z2) - 1);
    } else if (w == 1) {
        unsigned u = z1 & lowm;
        if (u)       dl = r - (31 - __clz(u));
        else if (z0) dl = r + 1 + __clz(z0);
        unsigned v = z1 & him;
        if (v)       dr = (__ffs(v) - 1) - r;
        else if (z2) dr = 32 - r + (__ffs(z2) - 1);
    } else {
        unsigned u = z2 & lowm;
        if (u)       dl = r - (31 - __clz(u));
        else if (z1) dl = r + 1 + __clz(z1);
        else if (z0) dl = r + 33 + __clz(z0);
        unsigned v = z2 & him;
        if (v) dr = (__ffs(v) - 1) - r;
    }
    return min(dl, dr);
}

__global__ void __launch_bounds__(256) k_binw(const void* __restrict__ tptr) {
    int wid = threadIdx.x >> 5, l = threadIdx.x & 31;
    int L = blockIdx.x * 8 + wid;
    int b = L / 9216;
    int n = L - b * 9216;
    int base = b * N3 + n * 96;

    int t0, t1, t2;
    if (g_is32) {
        const int* T = (const int*)tptr;
        t0 = T[base + l]; t1 = T[base + l + 32]; t2 = T[base + l + 64];
    } else {
        const long long* T = (const long long*)tptr;
        t0 = (int)T[base + l]; t1 = (int)T[base + l + 32]; t2 = (int)T[base + l + 64];
    }
    unsigned m1_0 = __ballot_sync(0xffffffffu, t0 == 1);
    unsigned m1_1 = __ballot_sync(0xffffffffu, t1 == 1);
    unsigned m1_2 = __ballot_sync(0xffffffffu, t2 == 1);
    unsigned m2_0 = __ballot_sync(0xffffffffu, t0 == 2);
    unsigned m2_1 = __ballot_sync(0xffffffffu, t1 == 2);
    unsigned m2_2 = __ballot_sync(0xffffffffu, t2 == 2);

    __shared__ int sc[2];
    if (threadIdx.x < 2) sc[threadIdx.x] = 0;
    __syncthreads();
    if (l == 0) {
        atomicAdd(&sc[0], __popc(m1_0) + __popc(m1_1) + __popc(m1_2));
        atomicAdd(&sc[1], __popc(m2_0) + __popc(m2_1) + __popc(m2_2));
    }
    __syncthreads();
    if (threadIdx.x == 0) {
        atomicAdd(&g_cnt[b * 2 + 0], sc[0]);
        atomicAdd(&g_cnt[b * 2 + 1], sc[1]);
    }

    #pragma unroll
    for (int ff = 0; ff < 4; ff++) {
        unsigned z0, z1, z2;
        if      (ff == 0) { z0 = ~m1_0; z1 = ~m1_1; z2 = ~m1_2; }
        else if (ff == 1) { z0 =  m1_0; z1 =  m1_1; z2 =  m1_2; }
        else if (ff == 2) { z0 = ~m2_0; z1 = ~m2_1; z2 = ~m2_2; }
        else              { z0 =  m2_0; z1 =  m2_1; z2 =  m2_2; }
        unsigned short* out = g_u16 + (size_t)(b * 4 + ff) * N3 + n * 96;
        int d0 = near_zero_dist(z0, z1, z2, 0, l);
        int d1 = near_zero_dist(z0, z1, z2, 1, l);
        int d2 = near_zero_dist(z0, z1, z2, 2, l);
        out[l]      = (d0 > 95) ? SENT : (unsigned short)(d0 * d0);
        out[l + 32] = (d1 > 95) ? SENT : (unsigned short)(d1 * d1);
        out[l + 64] = (d2 > 95) ? SENT : (unsigned short)(d2 * d2);
    }
}

// ------------------------------------------------- windowed min-conv core
__device__ __forceinline__ void minconv12(const float* __restrict__ shp,
                                          int j0, int j1,
                                          const float fi[12], float v[12]) {
    float m2a = -2.0f * (float)j0;
    int j = j0;
    for (; j + 1 <= j1; j += 2) {
        float a = shp[j * 32];
        float b = shp[j * 32 + 32];
        float m2b = m2a - 2.0f;
        #pragma unroll
        for (int k = 0; k < 12; k++)
            v[k] = fminf(v[k], fmaf(m2a, fi[k], a));
        #pragma unroll
        for (int k = 0; k < 12; k++)
            v[k] = fminf(v[k], fmaf(m2b, fi[k], b));
        m2a -= 4.0f;
    }
    if (j == j1) {
        float a = shp[j * 32];
        #pragma unroll
        for (int k = 0; k < 12; k++)
            v[k] = fminf(v[k], fmaf(m2a, fi[k], a));
    }
}

__device__ __forceinline__ int win_from_max(float m) {
    int R = (m >= 1e7f) ? 95 : ((int)floorf(sqrtf(m)) + 1);
    return min(R, 95);
}

// ---------------------------------------------------------------- H pass
__global__ void __launch_bounds__(256) k_pass_h() {
    __shared__ float sh[96 * 32];
    __shared__ int smax;
    int bid = blockIdx.x;
    int vb = bid / 288, rem = bid % 288;
    int s = rem / 3, wc = rem % 3;
    size_t base = (size_t)vb * N3 + (size_t)s * N2 + wc * 32;
    int tx = threadIdx.x & 31, ty = threadIdx.x >> 5;

    if (threadIdx.x == 0) smax = 0;
    __syncthreads();
    float mx = 0.f;
    #pragma unroll
    for (int r = ty; r < 96; r += 8) {
        unsigned u = g_u16[base + r * 96 + tx];
        float f = (u == SENT) ? BIGF : (float)u;
        mx = fmaxf(mx, f);
        sh[r * 32 + tx] = f + (float)(r * r);
    }
    #pragma unroll
    for (int off = 16; off; off >>= 1)
        mx = fmaxf(mx, __shfl_xor_sync(0xffffffffu, mx, off));
    if (tx == 0) atomicMax(&smax, __float_as_int(mx));
    __syncthreads();
    int R = win_from_max(__int_as_float(smax));

    int i0 = ty * 12;
    int j0 = max(0, i0 - R);
    int j1 = min(95, i0 + 11 + R);

    float v[12], fi[12];
    #pragma unroll
    for (int k = 0; k < 12; k++) { v[k] = 3.0e38f; fi[k] = (float)(i0 + k); }
    minconv12(sh + tx, j0, j1, fi, v);

    unsigned short* outp = g_u16 + base + (size_t)i0 * 96 + tx;
    #pragma unroll
    for (int k = 0; k < 12; k++) {
        float vi = v[k] + fi[k] * fi[k];
        outp[k * 96] = (vi >= 1e7f) ? SENT : (unsigned short)__float2int_rn(vi);
    }
}

// ------------------------------------------- fused D pass + softmax reduce
// Grid: 2(b) * 2(cls) * 96(h-slice) * 3(w-chunk) = 1152 blocks x 256.
// Each block: pos+neg fields of ONE class for its 96(d) x 32(w) tile.
__global__ void __launch_bounds__(256) k_fuse_d(const float* __restrict__ logits) {
    __shared__ float sh0[96 * 32];
    __shared__ float sh1[96 * 32];
    __shared__ int smaxi[2];
    __shared__ float swred[8];
    int bid = blockIdx.x;
    int b = bid / 576, rem = bid % 576;
    int cls = rem / 288, rem2 = rem % 288;
    int s = rem2 / 3, wc = rem2 % 3;
    int tx = threadIdx.x & 31, ty = threadIdx.x >> 5;
    unsigned nbase = (unsigned)s * 96 + wc * 32 + tx;   // voxel idx: + d*N2

    if (threadIdx.x < 2) smaxi[threadIdx.x] = 0;
    __syncthreads();

    const unsigned short* p0 = g_u16 + (size_t)(b * 4 + cls * 2 + 0) * N3 + nbase;
    const unsigned short* p1 = g_u16 + (size_t)(b * 4 + cls * 2 + 1) * N3 + nbase;
    float mx0 = 0.f, mx1 = 0.f;
    #pragma unroll
    for (int r = ty; r < 96; r += 8) {
        unsigned u0 = p0[(size_t)r * N2];
        unsigned u1 = p1[(size_t)r * N2];
        float f0 = (u0 == SENT) ? BIGF : (float)u0;
        float f1 = (u1 == SENT) ? BIGF : (float)u1;
        mx0 = fmaxf(mx0, f0); mx1 = fmaxf(mx1, f1);
        float r2 = (float)(r * r);
        sh0[r * 32 + tx] = f0 + r2;
        sh1[r * 32 + tx] = f1 + r2;
    }
    #pragma unroll
    for (int off = 16; off; off >>= 1) {
        mx0 = fmaxf(mx0, __shfl_xor_sync(0xffffffffu, mx0, off));
        mx1 = fmaxf(mx1, __shfl_xor_sync(0xffffffffu, mx1, off));
    }
    if (tx == 0) {
        atomicMax(&smaxi[0], __float_as_int(mx0));
        atomicMax(&smaxi[1], __float_as_int(mx1));
    }
    __syncthreads();
    int R0 = win_from_max(__int_as_float(smaxi[0]));
    int R1 = win_from_max(__int_as_float(smaxi[1]));

    int i0 = ty * 12;
    float fi[12], sd[12], v[12];
    #pragma unroll
    for (int k = 0; k < 12; k++) fi[k] = (float)(i0 + k);

    // pos field
    #pragma unroll
    for (int k = 0; k < 12; k++) v[k] = 3.0e38f;
    minconv12(sh0 + tx, max(0, i0 - R0), min(95, i0 + 11 + R0), fi, v);
    #pragma unroll
    for (int k = 0; k < 12; k++) sd[k] = -sqrtf(v[k] + fi[k] * fi[k]);
    // neg field
    #pragma unroll
    for (int k = 0; k < 12; k++) v[k] = 3.0e38f;
    minconv12(sh1 + tx, max(0, i0 - R1), min(95, i0 + 11 + R1), fi, v);
    #pragma unroll
    for (int k = 0; k < 12; k++) sd[k] += sqrtf(v[k] + fi[k] * fi[k]);

    // epilogue: softmax prob of this class, gated accumulate
    float gate = g_cnt[b * 2 + cls] > 0 ? 1.f : 0.f;
    const float* L = logits + (size_t)b * 3 * N3 + nbase + (size_t)i0 * N2;
    float acc = 0.f;
    #pragma unroll
    for (int k = 0; k < 12; k++) {
        float l0 = L[0], l1 = L[(size_t)N3], l2 = L[(size_t)2 * N3];
        L += N2;
        float m = fmaxf(l0, fmaxf(l1, l2));
        float e0 = __expf(l0 - m), e1 = __expf(l1 - m), e2 = __expf(l2 - m);
        float ec = cls ? e2 : e1;
        acc += (ec / (e0 + e1 + e2)) * sd[k];
    }
    acc *= gate;

    #pragma unroll
    for (int off = 16; off; off >>= 1)
        acc += __shfl_down_sync(0xffffffffu, acc, off);
    if (tx == 0) swred[ty] = acc;
    __syncthreads();
    if (threadIdx.x == 0) {
        float t = 0.f;
        #pragma unroll
        for (int i = 0; i < 8; i++) t += swred[i];
        g_part[bid] = t;
    }
}

// ---------------------------------------------------------------- final
__global__ void k_final(float* __restrict__ out) {
    __shared__ double sm[256];
    double s = 0.0;
    for (int i = threadIdx.x; i < 1152; i += 256) s += (double)g_part[i];
    sm[threadIdx.x] = s;
    __syncthreads();
    #pragma unroll
    for (int off = 128; off > 0; off >>= 1) {
        if (threadIdx.x < off) sm[threadIdx.x] += sm[threadIdx.x + off];
        __syncthreads();
    }
    if (threadIdx.x == 0)
        out[0] = (float)(sm[0] / (2.0 * (double)N3));
}

// ---------------------------------------------------------------- launch
extern "C" void kernel_launch(void* const* d_in, const int* in_sizes, int n_in,
                              void* d_out, int out_size) {
    const float* logits = (const float*)d_in[0];
    const void*  targets = d_in[1];
    float* out = (float*)d_out;
    (void)in_sizes; (void)n_in; (void)out_size;

    k_detect<<<1, 256>>>((const int*)targets);
    k_binw<<<2304, 256>>>(targets);
    k_pass_h<<<2304, 256>>>();
    k_fuse_d<<<1152, 256>>>(logits);
    k_final<<<1, 256>>>(out);
}